// round 1
// baseline (speedup 1.0000x reference)
#include <cuda_runtime.h>
#include <cuda_bf16.h>

#define BB 4
#define HH 16
#define SS 4096
#define DD 64
#define BH (BB*HH)
#define SPLIT 8
#define ROWS_P1 (SS/SPLIT)   // 512 rows per pass-1 block
#define CHUNK 8
#define TILE_ROWS 256        // rows per pass-2 block
#define SUBT 64              // rows per pass-2 inner iteration
#define KEPS 0.001f

// Scratch for per-split partial kv / ksum (device global: no allocations allowed)
__device__ float g_kv[BH][SPLIT][DD * DD];
__device__ float g_ksum[BH][SPLIT][DD];

// ---------------------------------------------------------------------------
// Pass 1: per (bh, split) block accumulates kv[d][e] and ksum[d] over its rows
// Thread tiling: 256 threads = 16 dq x 16 eq, each owns a 4x4 (d,e) register tile.
// ---------------------------------------------------------------------------
__global__ __launch_bounds__(256) void perf_pass1(
    const float* __restrict__ K,
    const float* __restrict__ V,
    const float* __restrict__ mask)
{
    const int bh = blockIdx.x / SPLIT;
    const int sp = blockIdx.x % SPLIT;
    const int b  = bh / HH;

    const float* Kp = K + (size_t)bh * SS * DD + (size_t)sp * ROWS_P1 * DD;
    const float* Vp = V + (size_t)bh * SS * DD + (size_t)sp * ROWS_P1 * DD;
    const float* Mp = mask + (size_t)b * SS + (size_t)sp * ROWS_P1;

    __shared__ float ks[CHUNK][DD];
    __shared__ float vs[CHUNK][DD];

    const int tid = threadIdx.x;
    const int eq  = tid & 15;   // e-tile index (e = eq*4 .. eq*4+3)
    const int dq  = tid >> 4;   // d-tile index (d = dq*4 .. dq*4+3)

    float acc[4][4];
#pragma unroll
    for (int i = 0; i < 4; i++)
#pragma unroll
        for (int j = 0; j < 4; j++) acc[i][j] = 0.f;

    float ksacc[4] = {0.f, 0.f, 0.f, 0.f};

    for (int c0 = 0; c0 < ROWS_P1; c0 += CHUNK) {
        // stage CHUNK rows of K (featurized+masked) and V into smem
#pragma unroll
        for (int i = tid; i < CHUNK * DD; i += 256) {
            const int r = i >> 6;
            const int d = i & 63;
            float kv_l = Kp[(size_t)(c0 + r) * DD + d];
            kv_l = fmaxf(kv_l, 0.f) + KEPS;
            ks[r][d] = kv_l * Mp[c0 + r];
            vs[r][d] = Vp[(size_t)(c0 + r) * DD + d];
        }
        __syncthreads();

#pragma unroll
        for (int r = 0; r < CHUNK; r++) {
            const float4 kk = *reinterpret_cast<const float4*>(&ks[r][dq * 4]);
            const float4 vv = *reinterpret_cast<const float4*>(&vs[r][eq * 4]);
            const float kd[4] = {kk.x, kk.y, kk.z, kk.w};
            const float ve[4] = {vv.x, vv.y, vv.z, vv.w};
#pragma unroll
            for (int i = 0; i < 4; i++)
#pragma unroll
                for (int j = 0; j < 4; j++)
                    acc[i][j] = fmaf(kd[i], ve[j], acc[i][j]);
            if (eq == 0) {
#pragma unroll
                for (int i = 0; i < 4; i++) ksacc[i] += kd[i];
            }
        }
        __syncthreads();
    }

    // write partials
    float* kvout = g_kv[bh][sp];
#pragma unroll
    for (int i = 0; i < 4; i++) {
        float4 o;
        o.x = acc[i][0]; o.y = acc[i][1]; o.z = acc[i][2]; o.w = acc[i][3];
        *reinterpret_cast<float4*>(&kvout[(dq * 4 + i) * DD + eq * 4]) = o;
    }
    if (eq == 0) {
#pragma unroll
        for (int i = 0; i < 4; i++) g_ksum[bh][sp][dq * 4 + i] = ksacc[i];
    }
}

// ---------------------------------------------------------------------------
// Pass 2: out[s,e] = (q'[s,:] . kv[:,e]) / (q'[s,:] . ksum)
// One block per (bh, 256-row tile). Thread tiling 16 eq x 16 rq, 4 e x 4 rows each.
// ---------------------------------------------------------------------------
__global__ __launch_bounds__(256) void perf_pass2(
    const float* __restrict__ Q,
    float* __restrict__ O)
{
    const int bh   = blockIdx.x >> 4;   // 16 tiles per head
    const int tile = blockIdx.x & 15;

    __shared__ float kv[DD][DD];        // [d][e]
    __shared__ float ksum[DD];
    __shared__ float qs[SUBT][DD + 1];  // +1 pad: kills bank conflicts on qs[r][d]
    __shared__ float denom[SUBT];

    const int tid = threadIdx.x;

    // reduce SPLIT partials into smem kv / ksum
    for (int i = tid; i < DD * DD; i += 256) {
        float s = 0.f;
#pragma unroll
        for (int p = 0; p < SPLIT; p++) s += g_kv[bh][p][i];
        (&kv[0][0])[i] = s;
    }
    if (tid < DD) {
        float s = 0.f;
#pragma unroll
        for (int p = 0; p < SPLIT; p++) s += g_ksum[bh][p][tid];
        ksum[tid] = s;
    }
    __syncthreads();

    const float* Qp = Q + (size_t)bh * SS * DD + (size_t)tile * TILE_ROWS * DD;
    float*       Op = O + (size_t)bh * SS * DD + (size_t)tile * TILE_ROWS * DD;

    const int eq = tid & 15;   // e = eq*4 .. eq*4+3
    const int rq = tid >> 4;   // rows rq*4 .. rq*4+3 within 64-row subtile

    for (int it = 0; it < TILE_ROWS / SUBT; it++) {
        // stage 64 q rows (featurized) into smem
        for (int i = tid; i < SUBT * DD; i += 256) {
            float v = Qp[(size_t)it * SUBT * DD + i];
            qs[i >> 6][i & 63] = fmaxf(v, 0.f) + KEPS;
        }
        __syncthreads();

        // denominator: each group of 4 lanes handles one row
        {
            const int row = tid >> 2;
            const int qtr = tid & 3;
            float s = 0.f;
#pragma unroll
            for (int j = 0; j < 16; j++)
                s = fmaf(qs[row][qtr * 16 + j], ksum[qtr * 16 + j], s);
            s += __shfl_xor_sync(0xFFFFFFFFu, s, 1);
            s += __shfl_xor_sync(0xFFFFFFFFu, s, 2);
            if (qtr == 0) denom[row] = s;
        }
        __syncthreads();

        // numerator: 4 rows x 4 e per thread
        float acc[4][4];
#pragma unroll
        for (int i = 0; i < 4; i++)
#pragma unroll
            for (int j = 0; j < 4; j++) acc[i][j] = 0.f;

#pragma unroll 8
        for (int d = 0; d < DD; d++) {
            const float4 kvv = *reinterpret_cast<const float4*>(&kv[d][eq * 4]);
            const float kve[4] = {kvv.x, kvv.y, kvv.z, kvv.w};
            float qr[4];
#pragma unroll
            for (int i = 0; i < 4; i++) qr[i] = qs[rq * 4 + i][d];
#pragma unroll
            for (int i = 0; i < 4; i++)
#pragma unroll
                for (int j = 0; j < 4; j++)
                    acc[i][j] = fmaf(qr[i], kve[j], acc[i][j]);
        }

        // scale by 1/denom and write out
#pragma unroll
        for (int i = 0; i < 4; i++) {
            const int row = rq * 4 + i;
            const float inv = 1.f / denom[row];
            float4 o;
            o.x = acc[i][0] * inv;
            o.y = acc[i][1] * inv;
            o.z = acc[i][2] * inv;
            o.w = acc[i][3] * inv;
            *reinterpret_cast<float4*>(
                &Op[(size_t)(it * SUBT + row) * DD + eq * 4]) = o;
        }
        __syncthreads();
    }
}

extern "C" void kernel_launch(void* const* d_in, const int* in_sizes, int n_in,
                              void* d_out, int out_size)
{
    const float* Q = (const float*)d_in[0];
    const float* K = (const float*)d_in[1];
    const float* V = (const float*)d_in[2];
    const float* M = (const float*)d_in[3];
    float* O = (float*)d_out;

    perf_pass1<<<BH * SPLIT, 256>>>(K, V, M);
    perf_pass2<<<BH * 16, 256>>>(Q, O);
}